// round 6
// baseline (speedup 1.0000x reference)
#include <cuda_runtime.h>

#define BS 8
#define CLS 4
#define CH 256
#define HH 128
#define WW 128
#define HW 16384
#define LL 19
#define TK 256

// Scratch for precomputed per-(b,l) rows: U[b,l,c] and t3[b,l,c]
__device__ float g_U[BS * LL * CH];
__device__ float g_T3[BS * LL * CH];

// ---------------------------------------------------------------------------
// Kernel A: per (l, b) block.
//   t_q[t]  = sum_c token_s[b,l,c] * W2[t,c]
//   U[c]    = sum_t t_q[t] * W1[t,c]
//   t3[o]   = sum_t token_s[b,l,t] * W3[o,t] + b3[o]
// ---------------------------------------------------------------------------
__global__ void precompute_kernel(const float* __restrict__ token_s,
                                  const float* __restrict__ W1,
                                  const float* __restrict__ W2,
                                  const float* __restrict__ W3,
                                  const float* __restrict__ b3) {
    const int l = blockIdx.x;
    const int b = blockIdx.y;
    const int tid = threadIdx.x;  // 0..255

    __shared__ float ts[TK];
    __shared__ float tq[TK];

    ts[tid] = token_s[(b * LL + l) * TK + tid];
    __syncthreads();

    // t_q row (thread = t)
    {
        const float* w2r = W2 + tid * TK;
        float acc = 0.f;
#pragma unroll 8
        for (int c = 0; c < TK; c++) acc += ts[c] * w2r[c];
        tq[tid] = acc;
    }
    __syncthreads();

    // U row (thread = c), coalesced over W1 columns
    {
        float accU = 0.f;
#pragma unroll 8
        for (int t = 0; t < TK; t++) accU += tq[t] * W1[t * CH + tid];
        g_U[(b * LL + l) * CH + tid] = accU;
    }
    // t3 row (thread = o)
    {
        const float* w3r = W3 + tid * TK;
        float acc3 = 0.f;
#pragma unroll 8
        for (int t = 0; t < TK; t++) acc3 += ts[t] * w3r[t];
        g_T3[(b * LL + l) * CH + tid] = acc3 + b3[tid];
    }
}

// ---------------------------------------------------------------------------
// Kernel B: fused mask*fea -> a = q.U -> softmax -> out = w.t3 + residual.
// Grid: (BS, 32). Block: 128 threads, each thread owns 4 consecutive pixels.
// gridDim.x = b so all 8 batches of one spatial tile are adjacent in launch
// order -> concurrent -> fea tile served from L2 for the 4 sharing batches.
// ---------------------------------------------------------------------------
__global__ void __launch_bounds__(128)
projector_main_kernel(const float* __restrict__ mask_t,
                      const float* __restrict__ fea_t,
                      float* __restrict__ out) {
    const int b = blockIdx.x;
    const int tile = blockIdx.y;
    const int tid = threadIdx.x;

    __shared__ float U_s[LL * CH];
    __shared__ float T3_s[LL * CH];

    // cooperative load of U / t3 (4864 floats each)
    {
        const float4* srcU = (const float4*)(g_U + b * LL * CH);
        const float4* srcT = (const float4*)(g_T3 + b * LL * CH);
        float4* dstU = (float4*)U_s;
        float4* dstT = (float4*)T3_s;
        for (int i = tid; i < LL * CH / 4; i += 128) {
            dstU[i] = srcU[i];
            dstT[i] = srcT[i];
        }
    }
    __syncthreads();

    const int p0 = tile * 512 + tid * 4;   // 4 consecutive pixels, same row
    const int h = p0 >> 7;
    const int w0 = p0 & 127;
    const int mh = h >> 1;
    const int mw0 = w0 >> 1;               // w0 % 4 == 0 -> mw0 even

    // nearest-upsampled mask values: pixels {0,1} use mw0, {2,3} use mw0+1
    float ma0, ma1, ma2, ma3, mb0, mb1, mb2, mb3;
    {
        const float* m0 = mask_t + ((b * CLS + 0) * 64 + mh) * 64;
        const float* m1 = mask_t + ((b * CLS + 1) * 64 + mh) * 64;
        const float* m2 = mask_t + ((b * CLS + 2) * 64 + mh) * 64;
        const float* m3 = mask_t + ((b * CLS + 3) * 64 + mh) * 64;
        ma0 = m0[mw0]; mb0 = m0[mw0 + 1];
        ma1 = m1[mw0]; mb1 = m1[mw0 + 1];
        ma2 = m2[mw0]; mb2 = m2[mw0 + 1];
        ma3 = m3[mw0]; mb3 = m3[mw0 + 1];
    }

    const int fb = (b & 1) * 4;  // fea batch group base: even b -> 0..3, odd -> 4..7
    const float4* fp0 = (const float4*)(fea_t + (size_t)(fb + 0) * CH * HW + p0);
    const float4* fp1 = (const float4*)(fea_t + (size_t)(fb + 1) * CH * HW + p0);
    const float4* fp2 = (const float4*)(fea_t + (size_t)(fb + 2) * CH * HW + p0);
    const float4* fp3 = (const float4*)(fea_t + (size_t)(fb + 3) * CH * HW + p0);

    float a0[LL], a1[LL], a2[LL], a3[LL];
#pragma unroll
    for (int l = 0; l < LL; l++) { a0[l] = 0.f; a1[l] = 0.f; a2[l] = 0.f; a3[l] = 0.f; }

    // ---- phase 1+2: q on the fly, accumulate a[l] = sum_c q*U[l,c] ----
    for (int c = 0; c < CH; c++) {
        const float4 f0 = fp0[c * (HW / 4)];
        const float4 f1 = fp1[c * (HW / 4)];
        const float4 f2 = fp2[c * (HW / 4)];
        const float4 f3 = fp3[c * (HW / 4)];
        const float q0 = 0.25f * (f0.x * ma0 + f1.x * ma1 + f2.x * ma2 + f3.x * ma3);
        const float q1 = 0.25f * (f0.y * ma0 + f1.y * ma1 + f2.y * ma2 + f3.y * ma3);
        const float q2 = 0.25f * (f0.z * mb0 + f1.z * mb1 + f2.z * mb2 + f3.z * mb3);
        const float q3 = 0.25f * (f0.w * mb0 + f1.w * mb1 + f2.w * mb2 + f3.w * mb3);
        const float* Uc = U_s + c;
#pragma unroll
        for (int l = 0; l < LL; l++) {
            const float u = Uc[l * CH];   // warp-broadcast LDS
            a0[l] += q0 * u;
            a1[l] += q1 * u;
            a2[l] += q2 * u;
            a3[l] += q3 * u;
        }
    }

    // ---- softmax over L (logits a/16), zero where a == 0 exactly ----
    {
        float e[LL];
#define SOFTMAX(A)                                                      \
        {                                                               \
            float mx = A[0];                                            \
            _Pragma("unroll") for (int l = 1; l < LL; l++) mx = fmaxf(mx, A[l]); \
            float s = 0.f;                                              \
            _Pragma("unroll") for (int l = 0; l < LL; l++) { e[l] = __expf((A[l] - mx) * 0.0625f); s += e[l]; } \
            const float inv = 1.f / s;                                  \
            _Pragma("unroll") for (int l = 0; l < LL; l++) A[l] = (A[l] == 0.f) ? 0.f : e[l] * inv; \
        }
        SOFTMAX(a0)
        SOFTMAX(a1)
        SOFTMAX(a2)
        SOFTMAX(a3)
#undef SOFTMAX
    }

    // ---- phase 3: out[c] = sum_l w[l]*t3[l,c] + fea_t[b,c,pixel] ----
    const float4* rp = (const float4*)(fea_t + (size_t)b * CH * HW + p0);
    float4* op = (float4*)(out + (size_t)b * CH * HW + p0);
    for (int c = 0; c < CH; c++) {
        const float* Tc = T3_s + c;
        float s0 = 0.f, s1 = 0.f, s2 = 0.f, s3 = 0.f;
#pragma unroll
        for (int l = 0; l < LL; l++) {
            const float t = Tc[l * CH];   // warp-broadcast LDS
            s0 += a0[l] * t;
            s1 += a1[l] * t;
            s2 += a2[l] * t;
            s3 += a3[l] * t;
        }
        const float4 r = rp[c * (HW / 4)];
        float4 o;
        o.x = s0 + r.x; o.y = s1 + r.y; o.z = s2 + r.z; o.w = s3 + r.w;
        op[c * (HW / 4)] = o;
    }
}

extern "C" void kernel_launch(void* const* d_in, const int* in_sizes, int n_in,
                              void* d_out, int out_size) {
    const float* mask_t  = (const float*)d_in[0];
    const float* fea_t   = (const float*)d_in[1];
    const float* token_s = (const float*)d_in[2];
    const float* W1      = (const float*)d_in[3];
    const float* W2      = (const float*)d_in[4];
    const float* W3      = (const float*)d_in[5];
    const float* b3      = (const float*)d_in[6];

    precompute_kernel<<<dim3(LL, BS), TK>>>(token_s, W1, W2, W3, b3);
    projector_main_kernel<<<dim3(BS, 32), 128>>>(mask_t, fea_t, (float*)d_out);
}

// round 7
// speedup vs baseline: 1.2219x; 1.2219x over previous
#include <cuda_runtime.h>

#define BS 8
#define CLS 4
#define CH 256
#define HH 128
#define WW 128
#define HW 16384
#define LL 19
#define LP 20   // padded L for float4 rows
#define TK 256

// Transposed precomputed rows: [b][c][LP] (l fastest, padded to 20)
__device__ float g_Ut[BS * CH * LP];
__device__ float g_T3t[BS * CH * LP];

// ---------------------------------------------------------------------------
// Kernel A: per (l, b) block.
//   t_q[t]  = sum_c token_s[b,l,c] * W2[t,c]
//   U[c]    = sum_t t_q[t] * W1[t,c]      -> g_Ut[b][c][l]
//   t3[o]   = sum_t token_s[b,l,t] * W3[o,t] + b3[o] -> g_T3t[b][o][l]
// ---------------------------------------------------------------------------
__global__ void precompute_kernel(const float* __restrict__ token_s,
                                  const float* __restrict__ W1,
                                  const float* __restrict__ W2,
                                  const float* __restrict__ W3,
                                  const float* __restrict__ b3) {
    const int l = blockIdx.x;
    const int b = blockIdx.y;
    const int tid = threadIdx.x;  // 0..255

    __shared__ float ts[TK];
    __shared__ float tq[TK];

    ts[tid] = token_s[(b * LL + l) * TK + tid];
    __syncthreads();

    {
        const float* w2r = W2 + tid * TK;
        float acc = 0.f;
#pragma unroll 8
        for (int c = 0; c < TK; c++) acc += ts[c] * w2r[c];
        tq[tid] = acc;
    }
    __syncthreads();

    {
        float accU = 0.f;
#pragma unroll 8
        for (int t = 0; t < TK; t++) accU += tq[t] * W1[t * CH + tid];
        g_Ut[(b * CH + tid) * LP + l] = accU;
    }
    {
        const float* w3r = W3 + tid * TK;
        float acc3 = 0.f;
#pragma unroll 8
        for (int t = 0; t < TK; t++) acc3 += ts[t] * w3r[t];
        g_T3t[(b * CH + tid) * LP + l] = acc3 + b3[tid];
    }
}

// ---------------------------------------------------------------------------
// Kernel B: fused mask*fea -> a = q.U -> softmax -> out = w.t3 + residual.
// Grid: (BS, 64). Block: 128 threads, each thread owns 2 consecutive pixels.
// One 20KB smem buffer reused: U (phase 1) then T3 (phase 3).
// ---------------------------------------------------------------------------
__global__ void __launch_bounds__(128)
projector_main_kernel(const float* __restrict__ mask_t,
                      const float* __restrict__ fea_t,
                      float* __restrict__ out) {
    const int b = blockIdx.x;
    const int tile = blockIdx.y;     // 0..63, 256 pixels each
    const int tid = threadIdx.x;

    __shared__ float sW[CH * LP];    // 20 KB, U then T3

    // load U (transposed) into smem: 5120 floats = 1280 float4
    {
        const float4* src = (const float4*)(g_Ut + b * CH * LP);
        float4* dst = (float4*)sW;
#pragma unroll
        for (int i = 0; i < CH * LP / 4 / 128; i++)
            dst[tid + i * 128] = src[tid + i * 128];
    }
    __syncthreads();

    const int p0 = tile * 256 + tid * 2;  // 2 consecutive pixels, same row
    const int h = p0 >> 7;
    const int w0 = p0 & 127;              // even
    const int mh = h >> 1;
    const int mw = w0 >> 1;               // both pixels share this mask column

    // mask values pre-scaled by 0.25 (exact power-of-2 scaling)
    float m0, m1, m2, m3;
    {
        const float* mp = mask_t + (b * CLS * 64 + mh) * 64 + mw;
        m0 = 0.25f * mp[0 * 64 * 64];
        m1 = 0.25f * mp[1 * 64 * 64];
        m2 = 0.25f * mp[2 * 64 * 64];
        m3 = 0.25f * mp[3 * 64 * 64];
    }

    const int fb = (b & 1) * 4;
    const float2* fp0 = (const float2*)(fea_t + (size_t)(fb + 0) * CH * HW + p0);
    const float2* fp1 = (const float2*)(fea_t + (size_t)(fb + 1) * CH * HW + p0);
    const float2* fp2 = (const float2*)(fea_t + (size_t)(fb + 2) * CH * HW + p0);
    const float2* fp3 = (const float2*)(fea_t + (size_t)(fb + 3) * CH * HW + p0);

    float a0[LL], a1[LL];
#pragma unroll
    for (int l = 0; l < LL; l++) { a0[l] = 0.f; a1[l] = 0.f; }

    // ---- phase 1: a[l] = sum_c q * U[c][l] ----
#pragma unroll 4
    for (int c = 0; c < CH; c++) {
        const float2 f0 = fp0[c * (HW / 2)];
        const float2 f1 = fp1[c * (HW / 2)];
        const float2 f2 = fp2[c * (HW / 2)];
        const float2 f3 = fp3[c * (HW / 2)];
        const float q0 = f0.x * m0 + f1.x * m1 + f2.x * m2 + f3.x * m3;
        const float q1 = f0.y * m0 + f1.y * m1 + f2.y * m2 + f3.y * m3;

        const float4* Uc = (const float4*)(sW + c * LP);
        float u[20];
        *(float4*)(u + 0)  = Uc[0];
        *(float4*)(u + 4)  = Uc[1];
        *(float4*)(u + 8)  = Uc[2];
        *(float4*)(u + 12) = Uc[3];
        *(float4*)(u + 16) = Uc[4];
#pragma unroll
        for (int l = 0; l < LL; l++) {
            a0[l] += q0 * u[l];
            a1[l] += q1 * u[l];
        }
    }

    // ---- softmax over L (logits a/16), zero where a == 0 exactly ----
    {
        float e[LL];
#define SOFTMAX(A)                                                      \
        {                                                               \
            float mx = A[0];                                            \
            _Pragma("unroll") for (int l = 1; l < LL; l++) mx = fmaxf(mx, A[l]); \
            float s = 0.f;                                              \
            _Pragma("unroll") for (int l = 0; l < LL; l++) { e[l] = __expf((A[l] - mx) * 0.0625f); s += e[l]; } \
            const float inv = 1.f / s;                                  \
            _Pragma("unroll") for (int l = 0; l < LL; l++) A[l] = (A[l] == 0.f) ? 0.f : e[l] * inv; \
        }
        SOFTMAX(a0)
        SOFTMAX(a1)
#undef SOFTMAX
    }

    // swap smem buffer: U -> T3
    __syncthreads();
    {
        const float4* src = (const float4*)(g_T3t + b * CH * LP);
        float4* dst = (float4*)sW;
#pragma unroll
        for (int i = 0; i < CH * LP / 4 / 128; i++)
            dst[tid + i * 128] = src[tid + i * 128];
    }
    __syncthreads();

    // ---- phase 3: out[c] = sum_l w[l]*t3[c][l] + fea_t[b,c,pixel] ----
    const float2* rp = (const float2*)(fea_t + (size_t)b * CH * HW + p0);
    float2* op = (float2*)(out + (size_t)b * CH * HW + p0);
#pragma unroll 4
    for (int c = 0; c < CH; c++) {
        const float4* Tc = (const float4*)(sW + c * LP);
        float t[20];
        *(float4*)(t + 0)  = Tc[0];
        *(float4*)(t + 4)  = Tc[1];
        *(float4*)(t + 8)  = Tc[2];
        *(float4*)(t + 12) = Tc[3];
        *(float4*)(t + 16) = Tc[4];
        float s0 = 0.f, s1 = 0.f;
#pragma unroll
        for (int l = 0; l < LL; l++) {
            s0 += a0[l] * t[l];
            s1 += a1[l] * t[l];
        }
        const float2 r = rp[c * (HW / 2)];
        float2 o;
        o.x = s0 + r.x;
        o.y = s1 + r.y;
        op[c * (HW / 2)] = o;
    }
}

extern "C" void kernel_launch(void* const* d_in, const int* in_sizes, int n_in,
                              void* d_out, int out_size) {
    const float* mask_t  = (const float*)d_in[0];
    const float* fea_t   = (const float*)d_in[1];
    const float* token_s = (const float*)d_in[2];
    const float* W1      = (const float*)d_in[3];
    const float* W2      = (const float*)d_in[4];
    const float* W3      = (const float*)d_in[5];
    const float* b3      = (const float*)d_in[6];

    precompute_kernel<<<dim3(LL, BS), TK>>>(token_s, W1, W2, W3, b3);
    projector_main_kernel<<<dim3(BS, 64), 128>>>(mask_t, fea_t, (float*)d_out);
}

// round 10
// speedup vs baseline: 1.3886x; 1.1364x over previous
#include <cuda_runtime.h>

#define BS 8
#define CLS 4
#define CH 256
#define HH 128
#define WW 128
#define HW 16384
#define LL 19
#define LP 20   // padded L for float4 rows
#define TK 256

// Static precomputes (input-independent shapes)
__device__ float g_M[CH * CH];     // M[c'][c] = sum_t W2[t][c'] * W1[t][c]
__device__ float g_W3T[TK * CH];   // W3T[t][o] = W3[o][t]
// Per-batch rows, transposed + padded: [b][c][LP] (l fastest)
__device__ float g_Ut[BS * CH * LP];
__device__ float g_T3t[BS * CH * LP];

// ---------------------------------------------------------------------------
// Kernel A0: M = W2^T * W1  (64 blocks, 4 rows of M each) and W3 transpose
// (16 blocks). All LDGs coalesced or uniform-broadcast.
// ---------------------------------------------------------------------------
__global__ void prep_static_kernel(const float* __restrict__ W1,
                                   const float* __restrict__ W2,
                                   const float* __restrict__ W3) {
    const int bid = blockIdx.x;
    const int tid = threadIdx.x;  // 0..255
    if (bid < 64) {
        const int c0 = bid * 4;
        float a0 = 0.f, a1 = 0.f, a2 = 0.f, a3 = 0.f;
#pragma unroll 4
        for (int t = 0; t < TK; t++) {
            const float w1 = W1[t * CH + tid];     // coalesced
            const float w20 = W2[t * TK + c0];     // uniform
            const float w21 = W2[t * TK + c0 + 1];
            const float w22 = W2[t * TK + c0 + 2];
            const float w23 = W2[t * TK + c0 + 3];
            a0 += w20 * w1; a1 += w21 * w1; a2 += w22 * w1; a3 += w23 * w1;
        }
        g_M[(c0 + 0) * CH + tid] = a0;
        g_M[(c0 + 1) * CH + tid] = a1;
        g_M[(c0 + 2) * CH + tid] = a2;
        g_M[(c0 + 3) * CH + tid] = a3;
    } else {
        const int tb = bid - 64;  // 0..15, 16 t-rows each
#pragma unroll
        for (int i = 0; i < 16; i++) {
            const int t = tb * 16 + i;
            g_W3T[t * CH + tid] = W3[tid * TK + t];  // write coalesced
        }
    }
}

// ---------------------------------------------------------------------------
// Kernel A: per-b U and t3 rows (transposed). Grid (2, BS), 256 threads.
//   wg0 (tid<128): U[l][c]  = sum_c' ts[l][c'] * M[c'][c]
//   wg1 (tid>=128): t3[l][o] = sum_t  ts[l][t]  * W3T[t][o] + b3[o]
// blockIdx.x selects which 128-wide half of the c/o output range.
// ---------------------------------------------------------------------------
__global__ void precompute_kernel(const float* __restrict__ token_s,
                                  const float* __restrict__ b3) {
    const int half = blockIdx.x;
    const int b = blockIdx.y;
    const int tid = threadIdx.x;

    __shared__ float ts_t[TK * LP];  // ts transposed: [c'][l], 20 KB

#pragma unroll
    for (int l = 0; l < LL; l++)
        ts_t[tid * LP + l] = token_s[(b * LL + l) * TK + tid];
    __syncthreads();

    const int wg = tid >> 7;             // 0 -> U, 1 -> t3
    const int c = half * 128 + (tid & 127);
    const float* __restrict__ Wp = (wg == 0) ? (g_M + c) : (g_W3T + c);

    float acc[LL];
#pragma unroll
    for (int l = 0; l < LL; l++) acc[l] = 0.f;

#pragma unroll 4
    for (int t = 0; t < TK; t++) {
        const float wv = Wp[t * CH];     // coalesced LDG
        const float4* tv = (const float4*)(ts_t + t * LP);
        float v[20];
        *(float4*)(v + 0)  = tv[0];
        *(float4*)(v + 4)  = tv[1];
        *(float4*)(v + 8)  = tv[2];
        *(float4*)(v + 12) = tv[3];
        *(float4*)(v + 16) = tv[4];
#pragma unroll
        for (int l = 0; l < LL; l++) acc[l] += v[l] * wv;
    }

    const float bias = (wg == 1) ? b3[c] : 0.f;
    float* dst = ((wg == 0) ? g_Ut : g_T3t) + (b * CH + c) * LP;
#pragma unroll
    for (int l = 0; l < LL; l++) dst[l] = acc[l] + bias;
}

// ---------------------------------------------------------------------------
// Kernel B: fused mask*fea -> a = q.U -> softmax -> out = w.t3 + residual.
// Grid (BS, 128): one image row per block, 128 threads = 1 pixel/thread.
// b fastest in grid so the 4 output batches sharing a fea group run
// concurrently on the same rows (L2 dedup of fea reads).
// ---------------------------------------------------------------------------
__global__ void __launch_bounds__(128, 6)
projector_main_kernel(const float* __restrict__ mask_t,
                      const float* __restrict__ fea_t,
                      float* __restrict__ out) {
    const int b = blockIdx.x;
    const int row = blockIdx.y;      // image row 0..127
    const int tid = threadIdx.x;     // column 0..127

    __shared__ float sW[CH * LP];    // 20 KB, U then T3

    {
        const float4* src = (const float4*)(g_Ut + b * CH * LP);
        float4* dst = (float4*)sW;
#pragma unroll
        for (int i = 0; i < CH * LP / 4 / 128; i++)
            dst[tid + i * 128] = src[tid + i * 128];
    }
    __syncthreads();

    const int pixel = row * WW + tid;
    const int mh = row >> 1;
    const int mw = tid >> 1;

    // mask values pre-scaled by 0.25 (exact power-of-2 scaling)
    float m0, m1, m2, m3;
    {
        const float* mp = mask_t + (b * CLS * 64 + mh) * 64 + mw;
        m0 = 0.25f * mp[0 * 64 * 64];
        m1 = 0.25f * mp[1 * 64 * 64];
        m2 = 0.25f * mp[2 * 64 * 64];
        m3 = 0.25f * mp[3 * 64 * 64];
    }

    const int fb = (b & 1) * 4;
    const float* fp0 = fea_t + (size_t)(fb + 0) * CH * HW + pixel;
    const float* fp1 = fea_t + (size_t)(fb + 1) * CH * HW + pixel;
    const float* fp2 = fea_t + (size_t)(fb + 2) * CH * HW + pixel;
    const float* fp3 = fea_t + (size_t)(fb + 3) * CH * HW + pixel;

    float a[LL];
#pragma unroll
    for (int l = 0; l < LL; l++) a[l] = 0.f;

    // ---- phase 1: a[l] = sum_c q * U[c][l] ----
#pragma unroll 4
    for (int c = 0; c < CH; c++) {
        const float f0 = fp0[c * HW];
        const float f1 = fp1[c * HW];
        const float f2 = fp2[c * HW];
        const float f3 = fp3[c * HW];
        const float q = f0 * m0 + f1 * m1 + f2 * m2 + f3 * m3;

        const float4* Uc = (const float4*)(sW + c * LP);
        float u[20];
        *(float4*)(u + 0)  = Uc[0];
        *(float4*)(u + 4)  = Uc[1];
        *(float4*)(u + 8)  = Uc[2];
        *(float4*)(u + 12) = Uc[3];
        *(float4*)(u + 16) = Uc[4];
#pragma unroll
        for (int l = 0; l < LL; l++) a[l] += q * u[l];
    }

    // ---- softmax over L (logits a/16), zero where a == 0 exactly ----
    {
        float e[LL];
        float mx = a[0];
#pragma unroll
        for (int l = 1; l < LL; l++) mx = fmaxf(mx, a[l]);
        float s = 0.f;
#pragma unroll
        for (int l = 0; l < LL; l++) { e[l] = __expf((a[l] - mx) * 0.0625f); s += e[l]; }
        const float inv = 1.f / s;
#pragma unroll
        for (int l = 0; l < LL; l++) a[l] = (a[l] == 0.f) ? 0.f : e[l] * inv;
    }

    // swap smem buffer: U -> T3
    __syncthreads();
    {
        const float4* src = (const float4*)(g_T3t + b * CH * LP);
        float4* dst = (float4*)sW;
#pragma unroll
        for (int i = 0; i < CH * LP / 4 / 128; i++)
            dst[tid + i * 128] = src[tid + i * 128];
    }
    __syncthreads();

    // ---- phase 3: out[c] = sum_l w[l]*t3[c][l] + fea_t[b,c,pixel] ----
    const float* rp = fea_t + (size_t)b * CH * HW + pixel;
    float* op = out + (size_t)b * CH * HW + pixel;
#pragma unroll 4
    for (int c = 0; c < CH; c++) {
        const float4* Tc = (const float4*)(sW + c * LP);
        float t[20];
        *(float4*)(t + 0)  = Tc[0];
        *(float4*)(t + 4)  = Tc[1];
        *(float4*)(t + 8)  = Tc[2];
        *(float4*)(t + 12) = Tc[3];
        *(float4*)(t + 16) = Tc[4];
        float s = 0.f;
#pragma unroll
        for (int l = 0; l < LL; l++) s += a[l] * t[l];
        op[c * HW] = s + rp[c * HW];
    }
}

extern "C" void kernel_launch(void* const* d_in, const int* in_sizes, int n_in,
                              void* d_out, int out_size) {
    const float* mask_t  = (const float*)d_in[0];
    const float* fea_t   = (const float*)d_in[1];
    const float* token_s = (const float*)d_in[2];
    const float* W1      = (const float*)d_in[3];
    const float* W2      = (const float*)d_in[4];
    const float* W3      = (const float*)d_in[5];
    const float* b3      = (const float*)d_in[6];

    prep_static_kernel<<<80, 256>>>(W1, W2, W3);
    precompute_kernel<<<dim3(2, BS), 256>>>(token_s, b3);
    projector_main_kernel<<<dim3(BS, 128), 128>>>(mask_t, fea_t, (float*)d_out);
}

// round 14
// speedup vs baseline: 1.7940x; 1.2920x over previous
#include <cuda_runtime.h>

#define BS 8
#define CLS 4
#define CH 256
#define HH 128
#define WW 128
#define HW 16384
#define LL 19
#define LP 20   // padded L for float4 rows
#define TK 256

// Static precomputes (input-independent shapes)
__device__ float g_M[CH * CH];     // M[c'][c] = sum_t W2[t][c'] * W1[t][c]
__device__ float g_W3T[TK * CH];   // W3T[t][o] = W3[o][t]
// Per-batch rows, transposed + padded: [b][c][LP] (l fastest)
__device__ float g_Ut[BS * CH * LP];
__device__ float g_T3t[BS * CH * LP];

// ---------------------------------------------------------------------------
// Kernel A0: M = W2^T * W1 (256 blocks, one M row each) + W3 transpose (16).
// Per M-block: stage W2 column c' in smem once, then coalesced W1 stream.
// ---------------------------------------------------------------------------
__global__ void prep_static_kernel(const float* __restrict__ W1,
                                   const float* __restrict__ W2,
                                   const float* __restrict__ W3) {
    const int bid = blockIdx.x;
    const int tid = threadIdx.x;  // 0..255
    if (bid < 256) {
        __shared__ float w2c[TK];
        w2c[tid] = W2[tid * TK + bid];   // column of W2 (one-time, latency ok)
        __syncthreads();
        float acc = 0.f;
#pragma unroll 8
        for (int t = 0; t < TK; t++)
            acc += w2c[t] * W1[t * CH + tid];   // coalesced, 8 LDGs in flight
        g_M[bid * CH + tid] = acc;
    } else {
        const int tb = bid - 256;  // 0..15, 16 t-rows each
#pragma unroll
        for (int i = 0; i < 16; i++) {
            const int t = tb * 16 + i;
            g_W3T[t * CH + tid] = W3[tid * TK + t];  // write coalesced
        }
    }
}

// ---------------------------------------------------------------------------
// Kernel A: per-b U and t3 rows (transposed). Grid (2, BS), 256 threads.
//   wg0 (tid<128): U[l][c]  = sum_c' ts[l][c'] * M[c'][c]
//   wg1 (tid>=128): t3[l][o] = sum_t  ts[l][t]  * W3T[t][o] + b3[o]
// ---------------------------------------------------------------------------
__global__ void precompute_kernel(const float* __restrict__ token_s,
                                  const float* __restrict__ b3) {
    const int half = blockIdx.x;
    const int b = blockIdx.y;
    const int tid = threadIdx.x;

    __shared__ float ts_t[TK * LP];  // ts transposed: [c'][l], 20 KB

#pragma unroll
    for (int l = 0; l < LL; l++)
        ts_t[tid * LP + l] = token_s[(b * LL + l) * TK + tid];
    __syncthreads();

    const int wg = tid >> 7;             // 0 -> U, 1 -> t3
    const int c = half * 128 + (tid & 127);
    const float* __restrict__ Wp = (wg == 0) ? (g_M + c) : (g_W3T + c);

    float acc[LL];
#pragma unroll
    for (int l = 0; l < LL; l++) acc[l] = 0.f;

#pragma unroll 4
    for (int t = 0; t < TK; t++) {
        const float wv = Wp[t * CH];     // coalesced LDG
        const float4* tv = (const float4*)(ts_t + t * LP);
        float v[20];
        *(float4*)(v + 0)  = tv[0];
        *(float4*)(v + 4)  = tv[1];
        *(float4*)(v + 8)  = tv[2];
        *(float4*)(v + 12) = tv[3];
        *(float4*)(v + 16) = tv[4];
#pragma unroll
        for (int l = 0; l < LL; l++) acc[l] += v[l] * wv;
    }

    const float bias = (wg == 1) ? b3[c] : 0.f;
    float* dst = ((wg == 0) ? g_Ut : g_T3t) + (b * CH + c) * LP;
#pragma unroll
    for (int l = 0; l < LL; l++) dst[l] = acc[l] + bias;
}

// ---------------------------------------------------------------------------
// Kernel B: fused mask*fea -> a = q.U -> softmax -> out = w.t3 + residual.
// Grid (BS, 64): 2 image rows per block, 256 threads = 1 pixel/thread.
// Both U and T3 staged in smem upfront (no mid-kernel swap barrier).
// b fastest in grid -> concurrent batches sharing a fea group hit L2.
// ---------------------------------------------------------------------------
__global__ void __launch_bounds__(256, 4)
projector_main_kernel(const float* __restrict__ mask_t,
                      const float* __restrict__ fea_t,
                      float* __restrict__ out) {
    const int b = blockIdx.x;
    const int tile = blockIdx.y;       // rows 2*tile, 2*tile+1
    const int tid = threadIdx.x;
    const int rsub = tid >> 7;
    const int col = tid & 127;
    const int row = tile * 2 + rsub;

    __shared__ float sU[CH * LP];      // 20 KB
    __shared__ float sT[CH * LP];      // 20 KB

    {
        const float4* srcU = (const float4*)(g_Ut + b * CH * LP);
        const float4* srcT = (const float4*)(g_T3t + b * CH * LP);
        float4* dstU = (float4*)sU;
        float4* dstT = (float4*)sT;
#pragma unroll
        for (int i = 0; i < CH * LP / 4 / 256; i++) {
            dstU[tid + i * 256] = srcU[tid + i * 256];
            dstT[tid + i * 256] = srcT[tid + i * 256];
        }
    }
    __syncthreads();

    const int pixel = row * WW + col;
    const int mh = row >> 1;
    const int mw = col >> 1;

    // mask values pre-scaled by 0.25 (exact power-of-2 scaling)
    float m0, m1, m2, m3;
    {
        const float* mp = mask_t + (b * CLS * 64 + mh) * 64 + mw;
        m0 = 0.25f * mp[0 * 64 * 64];
        m1 = 0.25f * mp[1 * 64 * 64];
        m2 = 0.25f * mp[2 * 64 * 64];
        m3 = 0.25f * mp[3 * 64 * 64];
    }

    const int fb = (b & 1) * 4;
    const float* fp = fea_t + (size_t)fb * CH * HW + pixel;

    float a[LL];
#pragma unroll
    for (int l = 0; l < LL; l++) a[l] = 0.f;

    // ---- phase 1: a[l] = sum_c q * U[c][l] ----
#pragma unroll 2
    for (int c = 0; c < CH; c++) {
        const float f0 = fp[c * HW + 0 * CH * HW];
        const float f1 = fp[c * HW + 1 * CH * HW];
        const float f2 = fp[c * HW + 2 * CH * HW];
        const float f3 = fp[c * HW + 3 * CH * HW];
        const float q = f0 * m0 + f1 * m1 + f2 * m2 + f3 * m3;

        const float4* Uc = (const float4*)(sU + c * LP);
        const float4 u0 = Uc[0], u1 = Uc[1], u2 = Uc[2], u3 = Uc[3], u4 = Uc[4];
        a[0] += q * u0.x;  a[1] += q * u0.y;  a[2] += q * u0.z;  a[3] += q * u0.w;
        a[4] += q * u1.x;  a[5] += q * u1.y;  a[6] += q * u1.z;  a[7] += q * u1.w;
        a[8] += q * u2.x;  a[9] += q * u2.y;  a[10] += q * u2.z; a[11] += q * u2.w;
        a[12] += q * u3.x; a[13] += q * u3.y; a[14] += q * u3.z; a[15] += q * u3.w;
        a[16] += q * u4.x; a[17] += q * u4.y; a[18] += q * u4.z;
    }

    // ---- softmax over L (logits a/16), zero where a == 0 exactly ----
    {
        float e[LL];
        float mx = a[0];
#pragma unroll
        for (int l = 1; l < LL; l++) mx = fmaxf(mx, a[l]);
        float s = 0.f;
#pragma unroll
        for (int l = 0; l < LL; l++) { e[l] = __expf((a[l] - mx) * 0.0625f); s += e[l]; }
        const float inv = 1.f / s;
#pragma unroll
        for (int l = 0; l < LL; l++) a[l] = (a[l] == 0.f) ? 0.f : e[l] * inv;
    }

    // ---- phase 3: out[c] = sum_l w[l]*t3[c][l] + fea_t[b,c,pixel] ----
    const float* rp = fea_t + (size_t)b * CH * HW + pixel;
    float* op = out + (size_t)b * CH * HW + pixel;
#pragma unroll 2
    for (int c = 0; c < CH; c++) {
        const float4* Tc = (const float4*)(sT + c * LP);
        const float4 t0 = Tc[0], t1 = Tc[1], t2 = Tc[2], t3v = Tc[3], t4 = Tc[4];
        float s = 0.f;
        s += a[0] * t0.x;  s += a[1] * t0.y;  s += a[2] * t0.z;  s += a[3] * t0.w;
        s += a[4] * t1.x;  s += a[5] * t1.y;  s += a[6] * t1.z;  s += a[7] * t1.w;
        s += a[8] * t2.x;  s += a[9] * t2.y;  s += a[10] * t2.z; s += a[11] * t2.w;
        s += a[12] * t3v.x; s += a[13] * t3v.y; s += a[14] * t3v.z; s += a[15] * t3v.w;
        s += a[16] * t4.x; s += a[17] * t4.y; s += a[18] * t4.z;
        op[c * HW] = s + rp[c * HW];
    }
}

extern "C" void kernel_launch(void* const* d_in, const int* in_sizes, int n_in,
                              void* d_out, int out_size) {
    const float* mask_t  = (const float*)d_in[0];
    const float* fea_t   = (const float*)d_in[1];
    const float* token_s = (const float*)d_in[2];
    const float* W1      = (const float*)d_in[3];
    const float* W2      = (const float*)d_in[4];
    const float* W3      = (const float*)d_in[5];
    const float* b3      = (const float*)d_in[6];

    prep_static_kernel<<<272, 256>>>(W1, W2, W3);
    precompute_kernel<<<dim3(2, BS), 256>>>(token_s, b3);
    projector_main_kernel<<<dim3(BS, 64), 256>>>(mask_t, fea_t, (float*)d_out);
}